// round 10
// baseline (speedup 1.0000x reference)
#include <cuda_runtime.h>
#include <cuda_fp8.h>
#include <math.h>
#include <stdint.h>

#define H        4
#define NN       10000
#define EMB      128
#define NB       4096
#define NQ       8192          // queries per head: [src(4096) | dst(4096)]
#define BQ       256           // queries per CTA -> 32x4 = 128 CTAs (single wave)
#define BN       128
#define NTILES   ((NN + BN - 1) / BN)   // 79
#define TOPK     9
#define NT       512           // 16 warps
#define RS       36            // row stride words (144B); 16B-banks: 9i mod 8 -> LDSM conflict-free
#define SB_LD    132

// smem byte offsets
#define QS_BYTES   (BQ * RS * 4)              // 36864
#define NS_BYTES   (BN * RS * 4)              // 18432 per buffer
#define OFF_N      (QS_BYTES)                 // 36864
#define OFF_SB     (QS_BYTES + 2 * NS_BYTES)  // 73728
#define SB_BYTES   (BQ * SB_LD * 4)           // 135168
#define OFF_Y2     (OFF_SB + SB_BYTES)        // 208896
#define OFF_MN     (OFF_Y2 + 4 * BN * 4)      // 210944  Mn[256][4] f32
#define OFF_TH     (OFF_MN + BQ * 4 * 4)      // 215040  th[256][2] f32
#define SMEM_BYTES (OFF_TH + BQ * 2 * 4)      // 217088

__device__ uint8_t g_e8[(size_t)H * NN * EMB];
__device__ float   g_y2[H * NN];
__device__ int     g_samples[H * NQ * 8];

// ---------------------------------------------------------------------------
// K1: convert embeds -> fp8 e4m3; y2 from the DEQUANTIZED values (fp32).
// ---------------------------------------------------------------------------
__global__ void prep_kernel(const float* __restrict__ embeds) {
    int gid  = blockIdx.x * 8 + (threadIdx.x >> 5);
    int lane = threadIdx.x & 31;
    if (gid >= H * NN) return;
    float4 v = ((const float4*)(embeds + (size_t)gid * EMB))[lane];
    __nv_fp8_e4m3 q0(v.x), q1(v.y), q2(v.z), q3(v.w);
    uint32_t packed = (uint32_t)q0.__x | ((uint32_t)q1.__x << 8)
                    | ((uint32_t)q2.__x << 16) | ((uint32_t)q3.__x << 24);
    ((uint32_t*)(g_e8 + (size_t)gid * EMB))[lane] = packed;
    float a = (float)q0, b = (float)q1, c = (float)q2, d = (float)q3;
    float s = a * a + b * b + c * c + d * d;
    #pragma unroll
    for (int o = 16; o > 0; o >>= 1) s += __shfl_xor_sync(0xffffffffu, s, o);
    if (lane == 0) g_y2[gid] = s;
}

// ---------------------------------------------------------------------------
__device__ __forceinline__ void mma_e4m3(float* c, const uint32_t* a, const uint32_t* b) {
    asm volatile(
        "mma.sync.aligned.m16n8k32.row.col.f32.e4m3.e4m3.f32 "
        "{%0,%1,%2,%3}, {%4,%5,%6,%7}, {%8,%9}, {%0,%1,%2,%3};"
        : "+f"(c[0]), "+f"(c[1]), "+f"(c[2]), "+f"(c[3])
        : "r"(a[0]), "r"(a[1]), "r"(a[2]), "r"(a[3]), "r"(b[0]), "r"(b[1]));
}
__device__ __forceinline__ void ldsm4(uint32_t* r, uint32_t addr) {
    asm volatile("ldmatrix.sync.aligned.m8n8.x4.shared.b16 {%0,%1,%2,%3}, [%4];"
        : "=r"(r[0]), "=r"(r[1]), "=r"(r[2]), "=r"(r[3]) : "r"(addr));
}

__device__ __forceinline__ void prefetch_tile(const uint8_t* __restrict__ E8,
                                              int h, int nbase, char* smem,
                                              int buf, int slot, int tid) {
    char* nb = smem + OFF_N + buf * NS_BYTES;
    int row  = tid >> 2;
    int part = tid & 3;
    int node = nbase + row;
    int valid = (node < NN) ? 16 : 0;
    const char* src = (const char*)(E8 + (size_t)(valid ? node : 0) * EMB) + part * 32;
    uint32_t dst = (uint32_t)__cvta_generic_to_shared(nb + row * (RS * 4) + part * 32);
    #pragma unroll
    for (int i = 0; i < 2; i++)
        asm volatile("cp.async.cg.shared.global [%0], [%1], 16, %2;"
                     :: "r"(dst + i * 16), "l"(src + i * 16), "r"(valid) : "memory");
    if (tid < BN) {
        int n2 = nbase + tid;
        float* y2s = (float*)(smem + OFF_Y2) + slot * BN;
        y2s[tid] = (n2 < NN) ? g_y2[h * NN + n2] : 3.0e37f;
    }
    asm volatile("cp.async.commit_group;" ::: "memory");
}

// ---------------------------------------------------------------------------
// K2: fp8 mma + ldmatrix frags + threshold-filtered top-9.
// grid (32, H), 512 threads (4x4 warps). Warp = 64q x 32n (one 32-col block).
// key = y2[n] - 2*dot (rank-equivalent to quantized d2).
// ---------------------------------------------------------------------------
__global__ __launch_bounds__(NT, 1)
void knn_kernel(const int* __restrict__ edges) {
    extern __shared__ __align__(16) char smem[];
    float* Sb  = (float*)(smem + OFF_SB);
    float* Mn  = (float*)(smem + OFF_MN);   // [256][4] block mins
    float* ths = (float*)(smem + OFF_TH);   // [256][2] published 9th-best per half

    const int tid  = threadIdx.x;
    const int lane = tid & 31;
    const int wid  = tid >> 5;
    const int g    = lane >> 2;            // 0..7
    const int t4   = lane & 3;             // 0..3
    const int R0   = (wid >> 2) * 64;      // warp rows
    const int C0   = (wid & 3) * 32;       // warp col block
    const int blk  = wid & 3;              // 32-col block index
    const int chalf = C0 >> 6;             // 0 or 1 (64-col half)

    const int h     = blockIdx.y;
    const int qbase = blockIdx.x * BQ;
    const uint8_t* E8 = g_e8 + (size_t)h * NN * EMB;

    const uint32_t qsBase = (uint32_t)__cvta_generic_to_shared(smem);
    const uint32_t nsBase = qsBase + OFF_N;

    // ---- gather query tile ----
    {
        int row = tid >> 1, part = tid & 1;
        int node = edges[qbase + row];     // flattened (2,4096) == query order
        const uint4* src = (const uint4*)(E8 + (size_t)node * EMB + part * 64);
        uint4* dst = (uint4*)(smem + row * (RS * 4) + part * 64);
        #pragma unroll
        for (int i = 0; i < 4; i++) dst[i] = src[i];
    }
    // ---- init thresholds ----
    if (tid < BQ * 2) ths[tid] = 3.0e38f;

    float bk[TOPK];
    int   bi[TOPK];
    #pragma unroll
    for (int r = 0; r < TOPK; r++) { bk[r] = 3.0e38f; bi[r] = 0; }

    prefetch_tile(E8, h, 0, smem, 0, 0, tid);
    prefetch_tile(E8, h, BN, smem, 1, 1, tid);

    // ldmatrix per-lane base addresses
    const uint32_t aOff = (uint32_t)((R0 + (lane & 15)) * (RS * 4) + (lane >> 4) * 16);
    const uint32_t bOff = (uint32_t)((C0 + ((lane >> 4) << 3) + (lane & 7)) * (RS * 4)
                                     + (((lane >> 3) & 1) << 4));
    const uint32_t aBase = qsBase + aOff;

    const float* y2all = (const float*)(smem + OFF_Y2);
    const int srow = tid & 255, shalf = tid >> 8;   // owner: 2 threads/row

    for (int t = 0; t < NTILES; t++) {
        const int nbase = t * BN;
        if (t + 2 < NTILES)
            asm volatile("cp.async.wait_group 1;" ::: "memory");
        else
            asm volatile("cp.async.wait_group 0;" ::: "memory");
        __syncthreads();   // tile t + y2 + th updates visible; Sb/Mn free

        const uint32_t bBase = nsBase + (t & 1) * NS_BYTES + bOff;
        const float*   y2s  = y2all + (t & 3) * BN;

        // ---- tensor GEMM via ldmatrix frags ----
        float acc[4][4][4];
        #pragma unroll
        for (int mt = 0; mt < 4; mt++)
            #pragma unroll
            for (int nt = 0; nt < 4; nt++)
                #pragma unroll
                for (int r = 0; r < 4; r++) acc[mt][nt][r] = 0.0f;

        #pragma unroll
        for (int ks = 0; ks < 4; ks++) {
            uint32_t a[4][4], b[2][4];     // b[p] = {b2p0,b2p1,b2p+1 0,b2p+1 1}
            #pragma unroll
            for (int mt = 0; mt < 4; mt++)
                ldsm4(a[mt], aBase + mt * 16 * (RS * 4) + ks * 32);
            #pragma unroll
            for (int p = 0; p < 2; p++)
                ldsm4(b[p], bBase + p * 16 * (RS * 4) + ks * 32);
            #pragma unroll
            for (int mt = 0; mt < 4; mt++) {
                mma_e4m3(acc[mt][0], a[mt], &b[0][0]);
                mma_e4m3(acc[mt][1], a[mt], &b[0][2]);
                mma_e4m3(acc[mt][2], a[mt], &b[1][0]);
                mma_e4m3(acc[mt][3], a[mt], &b[1][2]);
            }
        }

        // ---- keys + quad block-min + filtered stores ----
        #pragma unroll
        for (int mt = 0; mt < 4; mt++) {
            const int r0 = R0 + mt * 16 + g;
            const int r1 = r0 + 8;
            float k0[8], k1[8];
            #pragma unroll
            for (int nt = 0; nt < 4; nt++) {
                int col = C0 + nt * 8 + t4 * 2;
                float y0 = y2s[col], y1 = y2s[col + 1];
                k0[nt * 2]     = y0 - 2.0f * acc[mt][nt][0];
                k0[nt * 2 + 1] = y1 - 2.0f * acc[mt][nt][1];
                k1[nt * 2]     = y0 - 2.0f * acc[mt][nt][2];
                k1[nt * 2 + 1] = y1 - 2.0f * acc[mt][nt][3];
            }
            float m0 = k0[0], m1 = k1[0];
            #pragma unroll
            for (int j = 1; j < 8; j++) { m0 = fminf(m0, k0[j]); m1 = fminf(m1, k1[j]); }
            m0 = fminf(m0, __shfl_xor_sync(0xffffffffu, m0, 1));
            m0 = fminf(m0, __shfl_xor_sync(0xffffffffu, m0, 2));
            m1 = fminf(m1, __shfl_xor_sync(0xffffffffu, m1, 1));
            m1 = fminf(m1, __shfl_xor_sync(0xffffffffu, m1, 2));
            if (t4 == 0) {
                Mn[r0 * 4 + blk] = m0;
                Mn[r1 * 4 + blk] = m1;
            }
            float th0 = ths[r0 * 2 + chalf];
            float th1 = ths[r1 * 2 + chalf];
            if (m0 <= th0) {
                #pragma unroll
                for (int nt = 0; nt < 4; nt++)
                    *(float2*)(Sb + r0 * SB_LD + C0 + nt * 8 + t4 * 2) =
                        make_float2(k0[nt * 2], k0[nt * 2 + 1]);
            }
            if (m1 <= th1) {
                #pragma unroll
                for (int nt = 0; nt < 4; nt++)
                    *(float2*)(Sb + r1 * SB_LD + C0 + nt * 8 + t4 * 2) =
                        make_float2(k1[nt * 2], k1[nt * 2 + 1]);
            }
        }
        __syncthreads();   // Sb/Mn visible; N[t&1] free

        // ---- prefetch t+2 into the freed node buffer ----
        if (t + 2 < NTILES)
            prefetch_tile(E8, h, nbase + 2 * BN, smem, t & 1, (t + 2) & 3, tid);

        // ---- owner: check its 2 block mins, scan only passing blocks ----
        {
            float2 mm = *(const float2*)(Mn + srow * 4 + shalf * 2);
            float bmin[2] = {mm.x, mm.y};
            #pragma unroll
            for (int bb = 0; bb < 2; bb++) {
                if (bmin[bb] <= bk[TOPK - 1]) {
                    const int cb = shalf * 64 + bb * 32;
                    const float4* rowp = (const float4*)(Sb + srow * SB_LD + cb);
                    const int ibase = nbase + cb;
                    #pragma unroll
                    for (int n4 = 0; n4 < 8; n4++) {
                        float4 kv = rowp[n4];
                        float qmin = fminf(fminf(kv.x, kv.y), fminf(kv.z, kv.w));
                        if (qmin < bk[TOPK - 1]) {
                            float ks4[4] = {kv.x, kv.y, kv.z, kv.w};
                            #pragma unroll
                            for (int u = 0; u < 4; u++) {
                                float key = ks4[u];
                                if (key < bk[TOPK - 1]) {  // strict <: ascending order keeps lower idx
                                    bk[TOPK - 1] = key;
                                    bi[TOPK - 1] = ibase + n4 * 4 + u;
                                    #pragma unroll
                                    for (int r = TOPK - 1; r > 0; r--) {
                                        if (bk[r] < bk[r - 1]) {
                                            float tk = bk[r]; bk[r] = bk[r - 1]; bk[r - 1] = tk;
                                            int   ti = bi[r]; bi[r] = bi[r - 1]; bi[r - 1] = ti;
                                        }
                                    }
                                }
                            }
                        }
                    }
                }
            }
            ths[srow * 2 + shalf] = bk[TOPK - 1];   // publish (read after next barrier)
        }
    }

    // ---- merge the two half-lists per row (exact (key,idx) lexicographic) ----
    __syncthreads();                        // scans done; Sb reusable as scratch
    float* mk = Sb;                         // [512][9] keys
    int*   mi = (int*)(Sb + NT * TOPK);     // [512][9] indices
    #pragma unroll
    for (int r = 0; r < TOPK; r++) { mk[tid * TOPK + r] = bk[r]; mi[tid * TOPK + r] = bi[r]; }
    __syncthreads();
    if (tid < BQ) {
        const float* ka = mk + tid * TOPK;
        const int*   ia = mi + tid * TOPK;
        const float* kb = mk + (tid + 256) * TOPK;
        const int*   ib = mi + (tid + 256) * TOPK;
        int pa = 0, pb = 0;
        int sel[TOPK];
        #pragma unroll
        for (int r = 0; r < TOPK; r++) {
            bool ta = (ka[pa] < kb[pb]) || (ka[pa] == kb[pb] && ia[pa] < ib[pb]);
            sel[r] = ta ? ia[pa++] : ib[pb++];
        }
        int* out = g_samples + ((size_t)h * NQ + qbase + tid) * 8;
        #pragma unroll
        for (int r = 1; r < TOPK; r++) out[r - 1] = sel[r];  // drop rank 0 (self)
    }
}

// ---------------------------------------------------------------------------
// K3: epilogue. one block per batch edge, one warp per head. Exact fp32.
// ---------------------------------------------------------------------------
__global__ void epilogue_kernel(const float* __restrict__ embeds,
                                const float* __restrict__ field,
                                const float* __restrict__ unc,
                                const float* __restrict__ adj,
                                const int*   __restrict__ edges,
                                float*       __restrict__ out) {
    const int b    = blockIdx.x;
    const int h    = threadIdx.x >> 5;
    const int lane = threadIdx.x & 31;
    const int src  = edges[b];
    const int dst  = edges[NB + b];
    const float U  = unc[0];

    __shared__ float s_logit[H][16];
    __shared__ float s_dist[H][16];
    __shared__ float s_soft[H];

    const float* Eh = embeds + (size_t)h * NN * EMB;
    const float* Fh = field  + (size_t)h * NN * EMB;

    #pragma unroll
    for (int side = 0; side < 2; side++) {
        const int n     = (side == 0) ? src : dst;
        const int other = (side == 0) ? dst : src;
        const int* samp = g_samples + ((size_t)h * NQ + side * NB + b) * 8;
        float4 xn = ((const float4*)(Eh + (size_t)n * EMB))[lane];
        float4 gv = ((const float4*)(Fh + (size_t)other * EMB))[lane];
        for (int k = 0; k < 8; k++) {
            int s = samp[k];
            float4 es = ((const float4*)(Eh + (size_t)s * EMB))[lane];
            float dx = xn.x - es.x, dy = xn.y - es.y;
            float dz = xn.z - es.z, dw = xn.w - es.w;
            float dot = dx * gv.x + dy * gv.y + dz * gv.z + dw * gv.w;
            float ss  = dx * dx + dy * dy + dz * dz + dw * dw;
            #pragma unroll
            for (int o = 16; o > 0; o >>= 1) {
                dot += __shfl_xor_sync(0xffffffffu, dot, o);
                ss  += __shfl_xor_sync(0xffffffffu, ss,  o);
            }
            if (lane == 0) {
                float a = (side == 0) ? adj[(size_t)s * NN + other]
                                      : adj[(size_t)other * NN + s];
                s_logit[h][side * 8 + k] = dot + U * (a * 2.0f - 1.0f);
                s_dist [h][side * 8 + k] = sqrtf(ss);
            }
        }
    }
    __syncwarp();

    float w  = -3.0e38f, lg = 0.0f;
    if (lane < 16) { lg = s_logit[h][lane]; w = 1.0f - s_dist[h][lane]; }
    float m = w;
    #pragma unroll
    for (int o = 16; o > 0; o >>= 1) m = fmaxf(m, __shfl_xor_sync(0xffffffffu, m, o));
    m = fmaxf(m, 0.0f);
    float e   = (lane < 16) ? expf(w - m) : 0.0f;
    float num = e * lg;
    float den = e;
    #pragma unroll
    for (int o = 16; o > 0; o >>= 1) {
        num += __shfl_xor_sync(0xffffffffu, num, o);
        den += __shfl_xor_sync(0xffffffffu, den, o);
    }
    den += 8.0f * expf(-m);
    if (lane == 0) s_soft[h] = num / den;

    __syncthreads();
    if (threadIdx.x == 0) {
        float s = (s_soft[0] + s_soft[1] + s_soft[2] + s_soft[3]) * 0.25f;
        out[b] = 1.0f / (1.0f + expf(-s));
    }
}

// ---------------------------------------------------------------------------
extern "C" void kernel_launch(void* const* d_in, const int* in_sizes, int n_in,
                              void* d_out, int out_size) {
    (void)in_sizes; (void)n_in; (void)out_size;
    const float* embeds = (const float*)d_in[0];   // (4,10000,128) f32
    const float* field  = (const float*)d_in[1];   // (4,10000,128) f32
    const float* unc    = (const float*)d_in[2];   // (1,1,1) f32
    const float* adj    = (const float*)d_in[3];   // (10000,10000) f32
    const int*   edges  = (const int*)  d_in[4];   // (2,4096) i32
    float* out = (float*)d_out;                    // (4096,) f32

    cudaFuncSetAttribute(knn_kernel,
                         cudaFuncAttributeMaxDynamicSharedMemorySize, SMEM_BYTES);

    prep_kernel<<<(H * NN + 7) / 8, 256>>>(embeds);
    knn_kernel<<<dim3(NQ / BQ, H), NT, SMEM_BYTES>>>(edges);
    epilogue_kernel<<<NB, 128>>>(embeds, field, unc, adj, edges, out);
}

// round 12
// speedup vs baseline: 1.4020x; 1.4020x over previous
#include <cuda_runtime.h>
#include <cuda_fp8.h>
#include <math.h>
#include <stdint.h>

#define H        4
#define NN       10000
#define EMB      128
#define NB       4096
#define NQ       8192          // queries per head: [src(4096) | dst(4096)]
#define BQ       256           // queries per CTA -> 32x4 = 128 CTAs (single wave)
#define BN       128
#define NTILES   ((NN + BN - 1) / BN)   // 79
#define TOPK     9
#define NT       512           // 16 warps; each owns 16 query rows x 128 cols
#define RS       36            // row stride words
#define RB       144           // row stride bytes (LDSM conflict-free: 36w % 32 = 4)
#define SB_LD    132           // floats per key row: 128 cols + 4 pad

// smem byte offsets
#define QS_BYTES   (BQ * RB)                  // 36864
#define NS_BYTES   (BN * RB)                  // 18432 per buffer (x3)
#define OFF_N      (QS_BYTES)                 // 36864
#define OFF_SB     (OFF_N + 3 * NS_BYTES)     // 92160
#define SB_BYTES   (16 * 16 * SB_LD * 4)      // 135168
#define OFF_Y2     (OFF_SB + SB_BYTES)        // 227328
#define SMEM_BYTES (OFF_Y2 + 3 * BN * 4)      // 228864 (< 227KB limit)

__device__ uint8_t g_e8[(size_t)H * NN * EMB];
__device__ float   g_y2[H * NN];
__device__ int     g_samples[H * NQ * 8];

// ---------------------------------------------------------------------------
// K1: convert embeds -> fp8 e4m3; y2 from the DEQUANTIZED values (fp32).
// ---------------------------------------------------------------------------
__global__ void prep_kernel(const float* __restrict__ embeds) {
    int gid  = blockIdx.x * 8 + (threadIdx.x >> 5);
    int lane = threadIdx.x & 31;
    if (gid >= H * NN) return;
    float4 v = ((const float4*)(embeds + (size_t)gid * EMB))[lane];
    __nv_fp8_e4m3 q0(v.x), q1(v.y), q2(v.z), q3(v.w);
    uint32_t packed = (uint32_t)q0.__x | ((uint32_t)q1.__x << 8)
                    | ((uint32_t)q2.__x << 16) | ((uint32_t)q3.__x << 24);
    ((uint32_t*)(g_e8 + (size_t)gid * EMB))[lane] = packed;
    float a = (float)q0, b = (float)q1, c = (float)q2, d = (float)q3;
    float s = a * a + b * b + c * c + d * d;
    #pragma unroll
    for (int o = 16; o > 0; o >>= 1) s += __shfl_xor_sync(0xffffffffu, s, o);
    if (lane == 0) g_y2[gid] = s;
}

// ---------------------------------------------------------------------------
__device__ __forceinline__ void mma_e4m3(float* c, const uint32_t* a, const uint32_t* b) {
    asm volatile(
        "mma.sync.aligned.m16n8k32.row.col.f32.e4m3.e4m3.f32 "
        "{%0,%1,%2,%3}, {%4,%5,%6,%7}, {%8,%9}, {%0,%1,%2,%3};"
        : "+f"(c[0]), "+f"(c[1]), "+f"(c[2]), "+f"(c[3])
        : "r"(a[0]), "r"(a[1]), "r"(a[2]), "r"(a[3]), "r"(b[0]), "r"(b[1]));
}
__device__ __forceinline__ void ldsm4(uint32_t* r, uint32_t addr) {
    asm volatile("ldmatrix.sync.aligned.m8n8.x4.shared.b16 {%0,%1,%2,%3}, [%4];"
        : "=r"(r[0]), "=r"(r[1]), "=r"(r[2]), "=r"(r[3]) : "r"(addr));
}

// buf doubles as y2 slot (both t % 3)
__device__ __forceinline__ void prefetch_tile(const uint8_t* __restrict__ E8,
                                              int h, int nbase, char* smem,
                                              int buf, int tid) {
    char* nb = smem + OFF_N + buf * NS_BYTES;
    int row  = tid >> 2;
    int part = tid & 3;
    int node = nbase + row;
    int valid = (node < NN) ? 16 : 0;
    const char* src = (const char*)(E8 + (size_t)(valid ? node : 0) * EMB) + part * 32;
    uint32_t dst = (uint32_t)__cvta_generic_to_shared(nb + row * RB + part * 32);
    #pragma unroll
    for (int i = 0; i < 2; i++)
        asm volatile("cp.async.cg.shared.global [%0], [%1], 16, %2;"
                     :: "r"(dst + i * 16), "l"(src + i * 16), "r"(valid) : "memory");
    if (tid < BN) {
        int n2 = nbase + tid;
        float* y2s = (float*)(smem + OFF_Y2) + buf * BN;
        y2s[tid] = (n2 < NN) ? g_y2[h * NN + n2] : 3.0e37f;
    }
    asm volatile("cp.async.commit_group;" ::: "memory");
}

// ---------------------------------------------------------------------------
// K2: warp-autonomous fp8 mma + fused top-9. grid (32, H), 512 threads.
// Each warp: 16 query rows x 128 node cols per tile (16x m16n8k32, 4 k-steps).
// Keys exchanged through WARP-PRIVATE smem (__syncwarp only); one
// __syncthreads per tile guards the shared triple-buffered node tiles.
// key = y2[n] - 2*dot (rank-equivalent to quantized d2).
// ---------------------------------------------------------------------------
__global__ __launch_bounds__(NT, 1)
void knn_kernel(const int* __restrict__ edges) {
    extern __shared__ __align__(16) char smem[];
    const int tid  = threadIdx.x;
    const int lane = tid & 31;
    const int wid  = tid >> 5;
    const int g    = lane >> 2;            // 0..7
    const int t4   = lane & 3;             // 0..3
    const int R0   = wid * 16;             // this warp's query rows

    const int h     = blockIdx.y;
    const int qbase = blockIdx.x * BQ;
    const uint8_t* E8 = g_e8 + (size_t)h * NN * EMB;

    const uint32_t qsBase = (uint32_t)__cvta_generic_to_shared(smem);
    const uint32_t nsBase = qsBase + OFF_N;
    float* Sbw = (float*)(smem + OFF_SB) + wid * (16 * SB_LD);

    // ---- gather query tile (2 threads/row) ----
    {
        int row = tid >> 1, part = tid & 1;
        int node = edges[qbase + row];     // flattened (2,4096) == query order
        const uint4* src = (const uint4*)(E8 + (size_t)node * EMB + part * 64);
        uint4* dst = (uint4*)(smem + row * RB + part * 64);
        #pragma unroll
        for (int i = 0; i < 4; i++) dst[i] = src[i];
    }

    float bk[TOPK];
    int   bi[TOPK];
    #pragma unroll
    for (int r = 0; r < TOPK; r++) { bk[r] = 3.0e38f; bi[r] = 0; }

    prefetch_tile(E8, h, 0, smem, 0, tid);
    prefetch_tile(E8, h, BN, smem, 1, tid);

    // ldmatrix per-lane addresses (layout validated by R8<->R9 identical selection)
    const uint32_t aBase = qsBase + (uint32_t)((R0 + (lane & 15)) * RB + (lane >> 4) * 16);
    const uint32_t bOff  = (uint32_t)((((lane >> 4) << 3) + (lane & 7)) * RB
                                      + (((lane >> 3) & 1) << 4));

    const int srow = lane >> 1, shalf = lane & 1;  // scan: 2 lanes per warp-row
    const float* y2all = (const float*)(smem + OFF_Y2);

    int buf = 0;                                   // t % 3
    for (int t = 0; t < NTILES; t++) {
        const int nbase = t * BN;
        if (t < NTILES - 2)
            asm volatile("cp.async.wait_group 1;" ::: "memory");
        else
            asm volatile("cp.async.wait_group 0;" ::: "memory");
        __syncthreads();   // tile t data visible; all warps done reading tile t-1

        // ---- prefetch t+2 into buffer (t+2)%3 == (t-1)%3 (freed at barrier) ----
        if (t + 2 < NTILES) {
            int buf2 = buf + 2; if (buf2 >= 3) buf2 -= 3;
            prefetch_tile(E8, h, nbase + 2 * BN, smem, buf2, tid);
        }

        const uint32_t bBase = nsBase + buf * NS_BYTES + bOff;

        // ---- 16x m16n8k32 per k-step, A frag shared across all 16 ----
        float acc[16][4];
        #pragma unroll
        for (int nt = 0; nt < 16; nt++)
            #pragma unroll
            for (int r = 0; r < 4; r++) acc[nt][r] = 0.0f;

        #pragma unroll
        for (int ks = 0; ks < 4; ks++) {
            uint32_t a[4];
            ldsm4(a, aBase + ks * 32);
            #pragma unroll
            for (int p = 0; p < 8; p++) {
                uint32_t b[4];
                ldsm4(b, bBase + p * 16 * RB + ks * 32);
                mma_e4m3(acc[2 * p],     a, &b[0]);
                mma_e4m3(acc[2 * p + 1], a, &b[2]);
            }
        }

        // ---- keys -> warp-private buffer; no block barrier ----
        const float* y2s = y2all + buf * BN;
        #pragma unroll
        for (int nt = 0; nt < 16; nt++) {
            int col = nt * 8 + t4 * 2;
            float2 y = *(const float2*)(y2s + col);
            *(float2*)(Sbw + g * SB_LD + col) =
                make_float2(y.x - 2.0f * acc[nt][0], y.y - 2.0f * acc[nt][1]);
            *(float2*)(Sbw + (g + 8) * SB_LD + col) =
                make_float2(y.x - 2.0f * acc[nt][2], y.y - 2.0f * acc[nt][3]);
        }
        __syncwarp();

        // ---- scan own (row, half): 64 keys, float4 + quad-min early-out ----
        {
            const float4* rowp = (const float4*)(Sbw + srow * SB_LD + shalf * 64);
            const int ibase = nbase + shalf * 64;
            #pragma unroll 4
            for (int n4 = 0; n4 < 16; n4++) {
                float4 kv = rowp[n4];
                float qmin = fminf(fminf(kv.x, kv.y), fminf(kv.z, kv.w));
                if (qmin < bk[TOPK - 1]) {
                    float ks4[4] = {kv.x, kv.y, kv.z, kv.w};
                    #pragma unroll
                    for (int u = 0; u < 4; u++) {
                        float key = ks4[u];
                        if (key < bk[TOPK - 1]) {   // strict <: ties keep lower idx
                            bk[TOPK - 1] = key;
                            bi[TOPK - 1] = ibase + n4 * 4 + u;
                            #pragma unroll
                            for (int r = TOPK - 1; r > 0; r--) {
                                if (bk[r] < bk[r - 1]) {
                                    float tk = bk[r]; bk[r] = bk[r - 1]; bk[r - 1] = tk;
                                    int   ti = bi[r]; bi[r] = bi[r - 1]; bi[r - 1] = ti;
                                }
                            }
                        }
                    }
                }
            }
        }
        __syncwarp();      // all lanes done reading Sbw before next tile rewrites
        buf++; if (buf == 3) buf = 0;
    }

    // ---- merge the two half-lists per row via warp-private scratch ----
    {
        float* mk = Sbw;                    // [32][9] keys
        int*   mi = (int*)(Sbw + 32 * TOPK);
        #pragma unroll
        for (int r = 0; r < TOPK; r++) {
            mk[lane * TOPK + r] = bk[r];
            mi[lane * TOPK + r] = bi[r];
        }
        __syncwarp();
        if (shalf == 0) {
            const float* ka = mk + lane * TOPK;           // half 0 (lane even)
            const int*   ia = mi + lane * TOPK;
            const float* kb = mk + (lane + 1) * TOPK;     // half 1 (lane odd)
            const int*   ib = mi + (lane + 1) * TOPK;
            int pa = 0, pb = 0;
            int sel[TOPK];
            #pragma unroll
            for (int r = 0; r < TOPK; r++) {
                bool ta = (ka[pa] < kb[pb]) || (ka[pa] == kb[pb] && ia[pa] < ib[pb]);
                sel[r] = ta ? ia[pa++] : ib[pb++];
            }
            int* out = g_samples + ((size_t)h * NQ + qbase + R0 + srow) * 8;
            #pragma unroll
            for (int r = 1; r < TOPK; r++) out[r - 1] = sel[r];  // drop rank 0 (self)
        }
    }
}

// ---------------------------------------------------------------------------
// K3: epilogue. one block per batch edge, one warp per head. Exact fp32.
// ---------------------------------------------------------------------------
__global__ void epilogue_kernel(const float* __restrict__ embeds,
                                const float* __restrict__ field,
                                const float* __restrict__ unc,
                                const float* __restrict__ adj,
                                const int*   __restrict__ edges,
                                float*       __restrict__ out) {
    const int b    = blockIdx.x;
    const int h    = threadIdx.x >> 5;
    const int lane = threadIdx.x & 31;
    const int src  = edges[b];
    const int dst  = edges[NB + b];
    const float U  = unc[0];

    __shared__ float s_logit[H][16];
    __shared__ float s_dist[H][16];
    __shared__ float s_soft[H];

    const float* Eh = embeds + (size_t)h * NN * EMB;
    const float* Fh = field  + (size_t)h * NN * EMB;

    #pragma unroll
    for (int side = 0; side < 2; side++) {
        const int n     = (side == 0) ? src : dst;
        const int other = (side == 0) ? dst : src;
        const int* samp = g_samples + ((size_t)h * NQ + side * NB + b) * 8;
        float4 xn = ((const float4*)(Eh + (size_t)n * EMB))[lane];
        float4 gv = ((const float4*)(Fh + (size_t)other * EMB))[lane];
        for (int k = 0; k < 8; k++) {
            int s = samp[k];
            float4 es = ((const float4*)(Eh + (size_t)s * EMB))[lane];
            float dx = xn.x - es.x, dy = xn.y - es.y;
            float dz = xn.z - es.z, dw = xn.w - es.w;
            float dot = dx * gv.x + dy * gv.y + dz * gv.z + dw * gv.w;
            float ss  = dx * dx + dy * dy + dz * dz + dw * dw;
            #pragma unroll
            for (int o = 16; o > 0; o >>= 1) {
                dot += __shfl_xor_sync(0xffffffffu, dot, o);
                ss  += __shfl_xor_sync(0xffffffffu, ss,  o);
            }
            if (lane == 0) {
                float a = (side == 0) ? adj[(size_t)s * NN + other]
                                      : adj[(size_t)other * NN + s];
                s_logit[h][side * 8 + k] = dot + U * (a * 2.0f - 1.0f);
                s_dist [h][side * 8 + k] = sqrtf(ss);
            }
        }
    }
    __syncwarp();

    float w  = -3.0e38f, lg = 0.0f;
    if (lane < 16) { lg = s_logit[h][lane]; w = 1.0f - s_dist[h][lane]; }
    float m = w;
    #pragma unroll
    for (int o = 16; o > 0; o >>= 1) m = fmaxf(m, __shfl_xor_sync(0xffffffffu, m, o));
    m = fmaxf(m, 0.0f);
    float e   = (lane < 16) ? expf(w - m) : 0.0f;
    float num = e * lg;
    float den = e;
    #pragma unroll
    for (int o = 16; o > 0; o >>= 1) {
        num += __shfl_xor_sync(0xffffffffu, num, o);
        den += __shfl_xor_sync(0xffffffffu, den, o);
    }
    den += 8.0f * expf(-m);
    if (lane == 0) s_soft[h] = num / den;

    __syncthreads();
    if (threadIdx.x == 0) {
        float s = (s_soft[0] + s_soft[1] + s_soft[2] + s_soft[3]) * 0.25f;
        out[b] = 1.0f / (1.0f + expf(-s));
    }
}

// ---------------------------------------------------------------------------
extern "C" void kernel_launch(void* const* d_in, const int* in_sizes, int n_in,
                              void* d_out, int out_size) {
    (void)in_sizes; (void)n_in; (void)out_size;
    const float* embeds = (const float*)d_in[0];   // (4,10000,128) f32
    const float* field  = (const float*)d_in[1];   // (4,10000,128) f32
    const float* unc    = (const float*)d_in[2];   // (1,1,1) f32
    const float* adj    = (const float*)d_in[3];   // (10000,10000) f32
    const int*   edges  = (const int*)  d_in[4];   // (2,4096) i32
    float* out = (float*)d_out;                    // (4096,) f32

    cudaFuncSetAttribute(knn_kernel,
                         cudaFuncAttributeMaxDynamicSharedMemorySize, SMEM_BYTES);

    prep_kernel<<<(H * NN + 7) / 8, 256>>>(embeds);
    knn_kernel<<<dim3(NQ / BQ, H), NT, SMEM_BYTES>>>(edges);
    epilogue_kernel<<<NB, 128>>>(embeds, field, unc, adj, edges, out);
}

// round 13
// speedup vs baseline: 1.5269x; 1.0891x over previous
#include <cuda_runtime.h>
#include <cuda_fp8.h>
#include <cuda_fp16.h>
#include <math.h>
#include <stdint.h>

#define H        4
#define NN       10000
#define EMB      128
#define NB       4096
#define NQ       8192          // queries per head: [src(4096) | dst(4096)]
#define BQ       256           // queries per CTA -> 32x4 = 128 CTAs (single wave)
#define BN       128
#define NTILES   ((NN + BN - 1) / BN)   // 79
#define TOPK     9
#define NT       512           // 16 warps
#define RS       36            // row stride words (144B)
#define SB_LD    132

// smem byte offsets
#define QS_BYTES   (BQ * RS * 4)              // 36864
#define NS_BYTES   (BN * RS * 4)              // 18432 per buffer
#define OFF_N      (QS_BYTES)                 // 36864
#define OFF_SB     (QS_BYTES + 2 * NS_BYTES)  // 73728
#define SB_BYTES   (BQ * SB_LD * 4)           // 135168
#define OFF_Y2     (OFF_SB + SB_BYTES)        // 208896
#define SMEM_BYTES (OFF_Y2 + 4 * BN * 4)      // 210944

__device__ uint8_t g_e8[(size_t)H * NN * EMB];
__device__ float   g_y2[H * NN];
__device__ int     g_samples[H * NQ * 8];

// ---------------------------------------------------------------------------
// K1: convert embeds -> fp8 e4m3; y2 from the DEQUANTIZED values (fp32).
// ---------------------------------------------------------------------------
__global__ void prep_kernel(const float* __restrict__ embeds) {
    int gid  = blockIdx.x * 8 + (threadIdx.x >> 5);
    int lane = threadIdx.x & 31;
    if (gid >= H * NN) return;
    float4 v = ((const float4*)(embeds + (size_t)gid * EMB))[lane];
    __nv_fp8_e4m3 q0(v.x), q1(v.y), q2(v.z), q3(v.w);
    uint32_t packed = (uint32_t)q0.__x | ((uint32_t)q1.__x << 8)
                    | ((uint32_t)q2.__x << 16) | ((uint32_t)q3.__x << 24);
    ((uint32_t*)(g_e8 + (size_t)gid * EMB))[lane] = packed;
    float a = (float)q0, b = (float)q1, c = (float)q2, d = (float)q3;
    float s = a * a + b * b + c * c + d * d;
    #pragma unroll
    for (int o = 16; o > 0; o >>= 1) s += __shfl_xor_sync(0xffffffffu, s, o);
    if (lane == 0) g_y2[gid] = s;
}

// ---------------------------------------------------------------------------
// fp8 mma with FP16 accumulator (potentially 2x rate of f32-acc on sm_103).
// D reg0 = {row g, cols 2t4, 2t4+1}; reg1 = {row g+8, same cols}.
// ---------------------------------------------------------------------------
__device__ __forceinline__ void mma_e4m3_f16(uint32_t* c, const uint32_t* a,
                                             const uint32_t* b) {
    asm volatile(
        "mma.sync.aligned.m16n8k32.row.col.f16.e4m3.e4m3.f16 "
        "{%0,%1}, {%2,%3,%4,%5}, {%6,%7}, {%0,%1};"
        : "+r"(c[0]), "+r"(c[1])
        : "r"(a[0]), "r"(a[1]), "r"(a[2]), "r"(a[3]), "r"(b[0]), "r"(b[1]));
}

__device__ __forceinline__ void prefetch_tile(const uint8_t* __restrict__ E8,
                                              int h, int nbase, char* smem,
                                              int buf, int slot, int tid) {
    char* nb = smem + OFF_N + buf * NS_BYTES;
    int row  = tid >> 2;
    int part = tid & 3;
    int node = nbase + row;
    int valid = (node < NN) ? 16 : 0;
    const char* src = (const char*)(E8 + (size_t)(valid ? node : 0) * EMB) + part * 32;
    uint32_t dst = (uint32_t)__cvta_generic_to_shared(nb + row * (RS * 4) + part * 32);
    #pragma unroll
    for (int i = 0; i < 2; i++)
        asm volatile("cp.async.cg.shared.global [%0], [%1], 16, %2;"
                     :: "r"(dst + i * 16), "l"(src + i * 16), "r"(valid) : "memory");
    if (tid < BN) {
        int n2 = nbase + tid;
        float* y2s = (float*)(smem + OFF_Y2) + slot * BN;
        y2s[tid] = (n2 < NN) ? g_y2[h * NN + n2] : 3.0e37f;
    }
    asm volatile("cp.async.commit_group;" ::: "memory");
}

// ---------------------------------------------------------------------------
// K2: fp8 tensor GEMM (f16 acc) + fused top-9. grid (32, H), 512 threads.
// Warp computes 64q x 32n via 4x4 m16n8k32 tiles over K=128 (4 k-steps).
// key = y2[n] - 2*dot (rank-equivalent to quantized d2).
// ---------------------------------------------------------------------------
__global__ __launch_bounds__(NT, 1)
void knn_kernel(const int* __restrict__ edges) {
    extern __shared__ __align__(16) char smem[];
    float* Sb = (float*)(smem + OFF_SB);

    const int tid  = threadIdx.x;
    const int lane = tid & 31;
    const int wid  = tid >> 5;
    const int g    = lane >> 2;            // 0..7
    const int t4   = lane & 3;             // 0..3
    const int R0   = (wid >> 2) * 64;      // warp row: 0,64,128,192
    const int C0   = (wid & 3) * 32;       // warp col: 0,32,64,96

    const int h     = blockIdx.y;
    const int qbase = blockIdx.x * BQ;
    const uint8_t* E8 = g_e8 + (size_t)h * NN * EMB;

    // ---- gather query tile: 2 threads per row (fp8, padded stride) ----
    {
        int row = tid >> 1, part = tid & 1;
        int node = edges[qbase + row];     // flattened (2,4096) == query order
        const uint4* src = (const uint4*)(E8 + (size_t)node * EMB + part * 64);
        uint4* dst = (uint4*)(smem + row * (RS * 4) + part * 64);
        #pragma unroll
        for (int i = 0; i < 4; i++) dst[i] = src[i];
    }

    float bk[TOPK];
    int   bi[TOPK];
    #pragma unroll
    for (int r = 0; r < TOPK; r++) { bk[r] = 3.0e38f; bi[r] = 0; }

    prefetch_tile(E8, h, 0, smem, 0, 0, tid);
    prefetch_tile(E8, h, BN, smem, 1, 1, tid);

    const uint32_t* Qw = (const uint32_t*)smem;
    const float* y2all = (const float*)(smem + OFF_Y2);
    const int srow = tid & 255, shalf = tid >> 8;   // scan: 2 threads/row

    for (int t = 0; t < NTILES; t++) {
        const int nbase = t * BN;
        if (t + 2 < NTILES)
            asm volatile("cp.async.wait_group 1;" ::: "memory");
        else
            asm volatile("cp.async.wait_group 0;" ::: "memory");
        __syncthreads();   // tile t + y2 visible; prev scan done (Sb free)

        const uint32_t* Nw = (const uint32_t*)(smem + OFF_N + (t & 1) * NS_BYTES);
        const float*   y2s = y2all + (t & 3) * BN;

        // ---- tensor GEMM: 4x4 m16n8k32 per warp, 4 k-steps, f16 acc ----
        uint32_t acc[4][4][2];
        #pragma unroll
        for (int mt = 0; mt < 4; mt++)
            #pragma unroll
            for (int nt = 0; nt < 4; nt++) { acc[mt][nt][0] = 0u; acc[mt][nt][1] = 0u; }

        #pragma unroll
        for (int ks = 0; ks < 4; ks++) {
            const int kw = ks * 8;         // word offset (32 e4m3 = 8 words)
            uint32_t a[4][4], b[4][2];
            #pragma unroll
            for (int mt = 0; mt < 4; mt++) {
                const uint32_t* p = Qw + (R0 + mt * 16 + g) * RS + kw + t4;
                a[mt][0] = p[0];
                a[mt][1] = p[8 * RS];
                a[mt][2] = p[4];
                a[mt][3] = p[8 * RS + 4];
            }
            #pragma unroll
            for (int nt = 0; nt < 4; nt++) {
                const uint32_t* p = Nw + (C0 + nt * 8 + g) * RS + kw + t4;
                b[nt][0] = p[0];
                b[nt][1] = p[4];
            }
            #pragma unroll
            for (int mt = 0; mt < 4; mt++)
                #pragma unroll
                for (int nt = 0; nt < 4; nt++)
                    mma_e4m3_f16(acc[mt][nt], a[mt], b[nt]);
        }

        // ---- keys = y2 - 2*dot -> scan buffer (float2 stores) ----
        #pragma unroll
        for (int nt = 0; nt < 4; nt++) {
            int col = C0 + nt * 8 + t4 * 2;
            float y0 = y2s[col], y1 = y2s[col + 1];
            #pragma unroll
            for (int mt = 0; mt < 4; mt++) {
                int row = R0 + mt * 16 + g;
                float2 d0 = __half22float2(*(const __half2*)&acc[mt][nt][0]);
                float2 d1 = __half22float2(*(const __half2*)&acc[mt][nt][1]);
                *(float2*)(Sb + row * SB_LD + col) =
                    make_float2(y0 - 2.0f * d0.x, y1 - 2.0f * d0.y);
                *(float2*)(Sb + (row + 8) * SB_LD + col) =
                    make_float2(y0 - 2.0f * d1.x, y1 - 2.0f * d1.y);
            }
        }
        __syncthreads();   // Sb visible; N[t&1] free

        // ---- prefetch t+2 into the freed node buffer ----
        if (t + 2 < NTILES)
            prefetch_tile(E8, h, nbase + 2 * BN, smem, t & 1, (t + 2) & 3, tid);

        // ---- scan 64 cols/thread: float4 + fmin early-out ----
        {
            const float4* rowp = (const float4*)(Sb + srow * SB_LD + shalf * 64);
            const int ibase = nbase + shalf * 64;
            #pragma unroll 4
            for (int n4 = 0; n4 < 16; n4++) {
                float4 kv = rowp[n4];
                float qmin = fminf(fminf(kv.x, kv.y), fminf(kv.z, kv.w));
                if (qmin < bk[TOPK - 1]) {
                    float ks4[4] = {kv.x, kv.y, kv.z, kv.w};
                    #pragma unroll
                    for (int u = 0; u < 4; u++) {
                        float key = ks4[u];
                        if (key < bk[TOPK - 1]) {   // strict <: ties keep lower idx
                            bk[TOPK - 1] = key;
                            bi[TOPK - 1] = ibase + n4 * 4 + u;
                            #pragma unroll
                            for (int r = TOPK - 1; r > 0; r--) {
                                if (bk[r] < bk[r - 1]) {
                                    float tk = bk[r]; bk[r] = bk[r - 1]; bk[r - 1] = tk;
                                    int   ti = bi[r]; bi[r] = bi[r - 1]; bi[r - 1] = ti;
                                }
                            }
                        }
                    }
                }
            }
        }
    }

    // ---- merge the two half-lists per row (exact (key,idx) lexicographic) ----
    __syncthreads();                        // scans done; Sb reusable as scratch
    float* mk = Sb;                         // [512][9] keys
    int*   mi = (int*)(Sb + NT * TOPK);     // [512][9] indices
    #pragma unroll
    for (int r = 0; r < TOPK; r++) { mk[tid * TOPK + r] = bk[r]; mi[tid * TOPK + r] = bi[r]; }
    __syncthreads();
    if (tid < BQ) {
        const float* ka = mk + tid * TOPK;
        const int*   ia = mi + tid * TOPK;
        const float* kb = mk + (tid + 256) * TOPK;
        const int*   ib = mi + (tid + 256) * TOPK;
        int pa = 0, pb = 0;
        int sel[TOPK];
        #pragma unroll
        for (int r = 0; r < TOPK; r++) {
            bool ta = (ka[pa] < kb[pb]) || (ka[pa] == kb[pb] && ia[pa] < ib[pb]);
            sel[r] = ta ? ia[pa++] : ib[pb++];
        }
        int* out = g_samples + ((size_t)h * NQ + qbase + tid) * 8;
        #pragma unroll
        for (int r = 1; r < TOPK; r++) out[r - 1] = sel[r];  // drop rank 0 (self)
    }
}

// ---------------------------------------------------------------------------
// K3: epilogue. one block per batch edge, one warp per head. Exact fp32.
// ---------------------------------------------------------------------------
__global__ void epilogue_kernel(const float* __restrict__ embeds,
                                const float* __restrict__ field,
                                const float* __restrict__ unc,
                                const float* __restrict__ adj,
                                const int*   __restrict__ edges,
                                float*       __restrict__ out) {
    const int b    = blockIdx.x;
    const int h    = threadIdx.x >> 5;
    const int lane = threadIdx.x & 31;
    const int src  = edges[b];
    const int dst  = edges[NB + b];
    const float U  = unc[0];

    __shared__ float s_logit[H][16];
    __shared__ float s_dist[H][16];
    __shared__ float s_soft[H];

    const float* Eh = embeds + (size_t)h * NN * EMB;
    const float* Fh = field  + (size_t)h * NN * EMB;

    #pragma unroll
    for (int side = 0; side < 2; side++) {
        const int n     = (side == 0) ? src : dst;
        const int other = (side == 0) ? dst : src;
        const int* samp = g_samples + ((size_t)h * NQ + side * NB + b) * 8;
        float4 xn = ((const float4*)(Eh + (size_t)n * EMB))[lane];
        float4 gv = ((const float4*)(Fh + (size_t)other * EMB))[lane];
        for (int k = 0; k < 8; k++) {
            int s = samp[k];
            float4 es = ((const float4*)(Eh + (size_t)s * EMB))[lane];
            float dx = xn.x - es.x, dy = xn.y - es.y;
            float dz = xn.z - es.z, dw = xn.w - es.w;
            float dot = dx * gv.x + dy * gv.y + dz * gv.z + dw * gv.w;
            float ss  = dx * dx + dy * dy + dz * dz + dw * dw;
            #pragma unroll
            for (int o = 16; o > 0; o >>= 1) {
                dot += __shfl_xor_sync(0xffffffffu, dot, o);
                ss  += __shfl_xor_sync(0xffffffffu, ss,  o);
            }
            if (lane == 0) {
                float a = (side == 0) ? adj[(size_t)s * NN + other]
                                      : adj[(size_t)other * NN + s];
                s_logit[h][side * 8 + k] = dot + U * (a * 2.0f - 1.0f);
                s_dist [h][side * 8 + k] = sqrtf(ss);
            }
        }
    }
    __syncwarp();

    float w  = -3.0e38f, lg = 0.0f;
    if (lane < 16) { lg = s_logit[h][lane]; w = 1.0f - s_dist[h][lane]; }
    float m = w;
    #pragma unroll
    for (int o = 16; o > 0; o >>= 1) m = fmaxf(m, __shfl_xor_sync(0xffffffffu, m, o));
    m = fmaxf(m, 0.0f);
    float e   = (lane < 16) ? expf(w - m) : 0.0f;
    float num = e * lg;
    float den = e;
    #pragma unroll
    for (int o = 16; o > 0; o >>= 1) {
        num += __shfl_xor_sync(0xffffffffu, num, o);
        den += __shfl_xor_sync(0xffffffffu, den, o);
    }
    den += 8.0f * expf(-m);
    if (lane == 0) s_soft[h] = num / den;

    __syncthreads();
    if (threadIdx.x == 0) {
        float s = (s_soft[0] + s_soft[1] + s_soft[2] + s_soft[3]) * 0.25f;
        out[b] = 1.0f / (1.0f + expf(-s));
    }
}

// ---------------------------------------------------------------------------
extern "C" void kernel_launch(void* const* d_in, const int* in_sizes, int n_in,
                              void* d_out, int out_size) {
    (void)in_sizes; (void)n_in; (void)out_size;
    const float* embeds = (const float*)d_in[0];   // (4,10000,128) f32
    const float* field  = (const float*)d_in[1];   // (4,10000,128) f32
    const float* unc    = (const float*)d_in[2];   // (1,1,1) f32
    const float* adj    = (const float*)d_in[3];   // (10000,10000) f32
    const int*   edges  = (const int*)  d_in[4];   // (2,4096) i32
    float* out = (float*)d_out;                    // (4096,) f32

    cudaFuncSetAttribute(knn_kernel,
                         cudaFuncAttributeMaxDynamicSharedMemorySize, SMEM_BYTES);

    prep_kernel<<<(H * NN + 7) / 8, 256>>>(embeds);
    knn_kernel<<<dim3(NQ / BQ, H), NT, SMEM_BYTES>>>(edges);
    epilogue_kernel<<<NB, 128>>>(embeds, field, unc, adj, edges, out);
}